// round 6
// baseline (speedup 1.0000x reference)
#include <cuda_runtime.h>
#include <cuda_bf16.h>

#define HIDDEN 2048
#define INTER  1408
#define TOP_K  4

// Scratch for weighted intermediate activations: topk_w[e] * silu(gate)*up
__device__ float g_inter[TOP_K * INTER];

// ---------------------------------------------------------------------------
// Kernel 1: gate/up GEMV + SiLU for experts [eoff, eoff+2), with embedded L2
// prefetch of the corresponding down matrices (176 blocks x 64 KB = 11.53 MB
// per expert, exact). The 23 MB down fetch streams concurrently with the
// 46 MB gate/up stream inside this launch's DRAM window.
// grid: (176, 2), block: 256 threads (8 warps, 1 row per warp)
// ---------------------------------------------------------------------------
__global__ __launch_bounds__(256)
void moe_gate_up_kernel(const float* __restrict__ x,
                        const int*   __restrict__ topk_idx,
                        const float* __restrict__ topk_w,
                        const float* __restrict__ gate_all,
                        const float* __restrict__ up_all,
                        const float* __restrict__ down_all,
                        int eoff)
{
    __shared__ float4 x_s[HIDDEN / 4];   // 8 KB

    const int tid  = threadIdx.x;
    const int lane = tid & 31;
    const int warp = tid >> 5;
    const int e    = eoff + blockIdx.y;         // expert slot
    const long long ex = topk_idx[e];

    // --- Embedded prefetch of this expert's down block slice (fire & forget)
    {
        const char* dbase = reinterpret_cast<const char*>(
            down_all + ex * (long long)(HIDDEN * INTER));
        const long long off = (long long)blockIdx.x * 65536 + tid * 128;
        asm volatile("prefetch.global.L2 [%0];" :: "l"(dbase + off));
        asm volatile("prefetch.global.L2 [%0];" :: "l"(dbase + off + 32768));
    }

    // Stage x into shared memory: 512 float4 / 256 threads = 2 each
    const float4* x4 = reinterpret_cast<const float4*>(x);
    x_s[tid]       = x4[tid];
    x_s[tid + 256] = x4[tid + 256];
    __syncthreads();

    const int row = blockIdx.x * 8 + warp;      // 0..1407

    const float4* g4 = reinterpret_cast<const float4*>(
        gate_all + (ex * INTER + row) * (long long)HIDDEN);
    const float4* u4 = reinterpret_cast<const float4*>(
        up_all   + (ex * INTER + row) * (long long)HIDDEN);

    float gacc = 0.f, uacc = 0.f;
    // 512 float4 per row, 32 lanes -> 16 iterations
#pragma unroll
    for (int j = 0; j < 16; j++) {
        const int idx = j * 32 + lane;
        const float4 xv = x_s[idx];
        const float4 gv = __ldcs(g4 + idx);   // streaming: evict-first
        const float4 uv = __ldcs(u4 + idx);
        gacc += gv.x * xv.x + gv.y * xv.y + gv.z * xv.z + gv.w * xv.w;
        uacc += uv.x * xv.x + uv.y * xv.y + uv.z * xv.z + uv.w * xv.w;
    }

    // warp reduce
#pragma unroll
    for (int off = 16; off > 0; off >>= 1) {
        gacc += __shfl_xor_sync(0xFFFFFFFFu, gacc, off);
        uacc += __shfl_xor_sync(0xFFFFFFFFu, uacc, off);
    }

    if (lane == 0) {
        const float w = topk_w[e];
        const float silu = gacc / (1.0f + __expf(-gacc));
        g_inter[e * INTER + row] = w * silu * uacc;
    }
}

// ---------------------------------------------------------------------------
// Kernel 2: partial out[h] += dot(down[ex_{2p}][h][:], gi) +
//                             dot(down[ex_{2p+1}][h][:], gi)
// Warp per h over expert pair p. Down reads hit L2 (prefetched by kernel 1).
// Two commutative atomicAdds per h across the two pair-launches ->
// deterministic. out zeroed by cudaMemsetAsync.
// grid: 256, block: 256 threads (8 warps, 1 h per warp)
// ---------------------------------------------------------------------------
__global__ __launch_bounds__(256)
void moe_down_kernel(const int*   __restrict__ topk_idx,
                     const float* __restrict__ down_all,
                     float*       __restrict__ out,
                     int p)
{
    __shared__ float4 gi_s[2 * INTER / 4];   // 704 float4 = 11.25 KB

    const int tid  = threadIdx.x;
    const int lane = tid & 31;
    const int warp = tid >> 5;

    // Stage g_inter for experts 2p, 2p+1
    const float4* gi4 = reinterpret_cast<const float4*>(g_inter + 2 * p * INTER);
    for (int k = tid; k < 704; k += 256)
        gi_s[k] = gi4[k];
    __syncthreads();

    const int h = blockIdx.x * 8 + warp;     // 0..2047

    const long long e0 = topk_idx[2 * p];
    const long long e1 = topk_idx[2 * p + 1];
    const float4* d0 = reinterpret_cast<const float4*>(
        down_all + (e0 * HIDDEN + h) * (long long)INTER);
    const float4* d1 = reinterpret_cast<const float4*>(
        down_all + (e1 * HIDDEN + h) * (long long)INTER);

    float acc0 = 0.f, acc1 = 0.f;
    // 352 float4 per expert row, 32 lanes -> 11 iterations, 2 experts
#pragma unroll
    for (int j = 0; j < 11; j++) {
        const int idx = j * 32 + lane;
        const float4 a0 = __ldg(d0 + idx);
        const float4 a1 = __ldg(d1 + idx);
        const float4 v0 = gi_s[idx];
        const float4 v1 = gi_s[idx + 352];
        acc0 += a0.x * v0.x + a0.y * v0.y + a0.z * v0.z + a0.w * v0.w;
        acc1 += a1.x * v1.x + a1.y * v1.y + a1.z * v1.z + a1.w * v1.w;
    }

    float acc = acc0 + acc1;
#pragma unroll
    for (int off = 16; off > 0; off >>= 1)
        acc += __shfl_xor_sync(0xFFFFFFFFu, acc, off);

    if (lane == 0)
        atomicAdd(&out[h], acc);
}

extern "C" void kernel_launch(void* const* d_in, const int* in_sizes, int n_in,
                              void* d_out, int out_size)
{
    const float* x        = (const float*)d_in[0];   // (1, 2048, 1, 1)
    const int*   topk_idx = (const int*)  d_in[1];   // (4,)
    const float* topk_w   = (const float*)d_in[2];   // (4,)
    const float* gate_all = (const float*)d_in[3];   // (60, 1408, 2048)
    const float* up_all   = (const float*)d_in[4];   // (60, 1408, 2048)
    const float* down_all = (const float*)d_in[5];   // (60, 2048, 1408)
    float* out = (float*)d_out;                      // (1, 2048, 1, 1)

    // One side stream + two events, created once (host resources only; the
    // captured work is identical on every call).
    static cudaStream_t s1 = nullptr;
    static cudaEvent_t ev1 = nullptr, ev2 = nullptr;
    if (s1 == nullptr) {
        cudaStreamCreateWithFlags(&s1, cudaStreamNonBlocking);
        cudaEventCreateWithFlags(&ev1, cudaEventDisableTiming);
        cudaEventCreateWithFlags(&ev2, cudaEventDisableTiming);
    }

    dim3 grid1(INTER / 8, 2);

    // main stream (0): memset -> K1a -> ev1 -> K1b -> wait ev2 -> K2b
    // side stream s1 :                wait ev1 -> K2a -> ev2
    cudaMemsetAsync(out, 0, HIDDEN * sizeof(float));

    moe_gate_up_kernel<<<grid1, 256>>>(x, topk_idx, topk_w,
                                       gate_all, up_all, down_all, /*eoff=*/0);
    cudaEventRecord(ev1, 0);

    moe_gate_up_kernel<<<grid1, 256>>>(x, topk_idx, topk_w,
                                       gate_all, up_all, down_all, /*eoff=*/2);

    cudaStreamWaitEvent(s1, ev1, 0);
    moe_down_kernel<<<HIDDEN / 8, 256, 0, s1>>>(topk_idx, down_all, out, /*p=*/0);
    cudaEventRecord(ev2, s1);

    cudaStreamWaitEvent(0, ev2, 0);
    moe_down_kernel<<<HIDDEN / 8, 256>>>(topk_idx, down_all, out, /*p=*/1);
}

// round 7
// speedup vs baseline: 1.1750x; 1.1750x over previous
#include <cuda_runtime.h>
#include <cuda_bf16.h>

#define HIDDEN 2048
#define INTER  1408
#define TOP_K  4

// Scratch for weighted intermediate activations: topk_w[e] * silu(gate)*up
__device__ float g_inter[TOP_K * INTER];

// ---------------------------------------------------------------------------
// Kernel 1 (unchanged from the 25.3us version): gate/up GEMV + SiLU with
// embedded L2 prefetch of the down matrices. Block (bx, e) prefetches bytes
// [bx*65536, (bx+1)*65536) of down[topk_idx[e]] (176 x 64 KB = 11.53 MB per
// expert, exact), so the 46 MB down fetch streams concurrently with the
// 92 MB gate/up stream in one DRAM window.
// grid: (176, 4), block: 256 threads (8 warps, 1 row per warp)
// ---------------------------------------------------------------------------
__global__ __launch_bounds__(256)
void moe_gate_up_kernel(const float* __restrict__ x,
                        const int*   __restrict__ topk_idx,
                        const float* __restrict__ topk_w,
                        const float* __restrict__ gate_all,
                        const float* __restrict__ up_all,
                        const float* __restrict__ down_all)
{
    __shared__ float4 x_s[HIDDEN / 4];   // 8 KB

    const int tid  = threadIdx.x;
    const int lane = tid & 31;
    const int warp = tid >> 5;
    const int e    = blockIdx.y;                // expert slot 0..3
    const long long ex = topk_idx[e];

    // --- Embedded prefetch of this expert's down block slice (fire & forget)
    {
        const char* dbase = reinterpret_cast<const char*>(
            down_all + ex * (long long)(HIDDEN * INTER));
        const long long off = (long long)blockIdx.x * 65536 + tid * 128;
        asm volatile("prefetch.global.L2 [%0];" :: "l"(dbase + off));
        asm volatile("prefetch.global.L2 [%0];" :: "l"(dbase + off + 32768));
    }

    // Stage x into shared memory: 512 float4 / 256 threads = 2 each
    const float4* x4 = reinterpret_cast<const float4*>(x);
    x_s[tid]       = x4[tid];
    x_s[tid + 256] = x4[tid + 256];
    __syncthreads();

    const int row = blockIdx.x * 8 + warp;      // 0..1407

    const float4* g4 = reinterpret_cast<const float4*>(
        gate_all + (ex * INTER + row) * (long long)HIDDEN);
    const float4* u4 = reinterpret_cast<const float4*>(
        up_all   + (ex * INTER + row) * (long long)HIDDEN);

    float gacc = 0.f, uacc = 0.f;
    // 512 float4 per row, 32 lanes -> 16 iterations
#pragma unroll
    for (int j = 0; j < 16; j++) {
        const int idx = j * 32 + lane;
        const float4 xv = x_s[idx];
        const float4 gv = __ldcs(g4 + idx);   // streaming: evict-first
        const float4 uv = __ldcs(u4 + idx);
        gacc += gv.x * xv.x + gv.y * xv.y + gv.z * xv.z + gv.w * xv.w;
        uacc += uv.x * xv.x + uv.y * xv.y + uv.z * xv.z + uv.w * xv.w;
    }

    // warp reduce
#pragma unroll
    for (int off = 16; off > 0; off >>= 1) {
        gacc += __shfl_xor_sync(0xFFFFFFFFu, gacc, off);
        uacc += __shfl_xor_sync(0xFFFFFFFFu, uacc, off);
    }

    if (lane == 0) {
        const float w = topk_w[e];
        const float silu = gacc / (1.0f + __expf(-gacc));
        g_inter[e * INTER + row] = w * silu * uacc;
    }
}

// ---------------------------------------------------------------------------
// Kernel 2: out[h] = sum_e dot(down[ex_e][h][:], g_inter[e][:])
// One warp per h across ALL 4 experts: 44 fully-unrolled independent LDG.128
// per warp (deep MLP against L2 hit latency). All of g_inter (22.5 KB)
// staged in smem per block. Single write per h, fixed expert order ->
// deterministic, no memset, no atomics.
// grid: 256, block: 256 threads (8 warps, 1 h per warp)
// ---------------------------------------------------------------------------
__global__ __launch_bounds__(256)
void moe_down_kernel(const int*   __restrict__ topk_idx,
                     const float* __restrict__ down_all,
                     float*       __restrict__ out)
{
    __shared__ float4 gi_s[TOP_K * INTER / 4];   // 1408 float4 = 22.5 KB

    const int tid  = threadIdx.x;
    const int lane = tid & 31;
    const int warp = tid >> 5;

    // Stage g_inter: 1408 float4 / 256 threads
    const float4* gi4 = reinterpret_cast<const float4*>(g_inter);
    for (int k = tid; k < TOP_K * INTER / 4; k += 256)
        gi_s[k] = gi4[k];
    __syncthreads();

    const int h = blockIdx.x * 8 + warp;     // 0..2047

    const long long e0 = topk_idx[0];
    const long long e1 = topk_idx[1];
    const long long e2 = topk_idx[2];
    const long long e3 = topk_idx[3];
    const float4* d0 = reinterpret_cast<const float4*>(down_all + (e0 * HIDDEN + h) * (long long)INTER);
    const float4* d1 = reinterpret_cast<const float4*>(down_all + (e1 * HIDDEN + h) * (long long)INTER);
    const float4* d2 = reinterpret_cast<const float4*>(down_all + (e2 * HIDDEN + h) * (long long)INTER);
    const float4* d3 = reinterpret_cast<const float4*>(down_all + (e3 * HIDDEN + h) * (long long)INTER);

    float acc0 = 0.f, acc1 = 0.f, acc2 = 0.f, acc3 = 0.f;
    // 352 float4 per expert row, 32 lanes -> 11 iterations x 4 experts
#pragma unroll
    for (int j = 0; j < 11; j++) {
        const int idx = j * 32 + lane;
        const float4 a0 = __ldg(d0 + idx);
        const float4 a1 = __ldg(d1 + idx);
        const float4 a2 = __ldg(d2 + idx);
        const float4 a3 = __ldg(d3 + idx);
        const float4 v0 = gi_s[idx];
        const float4 v1 = gi_s[idx + 352];
        const float4 v2 = gi_s[idx + 704];
        const float4 v3 = gi_s[idx + 1056];
        acc0 += a0.x * v0.x + a0.y * v0.y + a0.z * v0.z + a0.w * v0.w;
        acc1 += a1.x * v1.x + a1.y * v1.y + a1.z * v1.z + a1.w * v1.w;
        acc2 += a2.x * v2.x + a2.y * v2.y + a2.z * v2.z + a2.w * v2.w;
        acc3 += a3.x * v3.x + a3.y * v3.y + a3.z * v3.z + a3.w * v3.w;
    }

    float acc = (acc0 + acc1) + (acc2 + acc3);
#pragma unroll
    for (int off = 16; off > 0; off >>= 1)
        acc += __shfl_xor_sync(0xFFFFFFFFu, acc, off);

    if (lane == 0)
        out[h] = acc;
}

extern "C" void kernel_launch(void* const* d_in, const int* in_sizes, int n_in,
                              void* d_out, int out_size)
{
    const float* x        = (const float*)d_in[0];   // (1, 2048, 1, 1)
    const int*   topk_idx = (const int*)  d_in[1];   // (4,)
    const float* topk_w   = (const float*)d_in[2];   // (4,)
    const float* gate_all = (const float*)d_in[3];   // (60, 1408, 2048)
    const float* up_all   = (const float*)d_in[4];   // (60, 1408, 2048)
    const float* down_all = (const float*)d_in[5];   // (60, 2048, 1408)
    float* out = (float*)d_out;                      // (1, 2048, 1, 1)

    dim3 grid1(INTER / 8, TOP_K);
    moe_gate_up_kernel<<<grid1, 256>>>(x, topk_idx, topk_w,
                                       gate_all, up_all, down_all);

    moe_down_kernel<<<HIDDEN / 8, 256>>>(topk_idx, down_all, out);
}